// round 14
// baseline (speedup 1.0000x reference)
#include <cuda_runtime.h>
#include <math.h>

#define NB 4
#define NE 100000
#define NT 100000
#define ND 64
#define HSZ 256          // hop-1 (b,obj) hash, direct-slot; key stored +1, 0 = empty
#define HSZ2 1024        // output hash; key stored +1, 0 = empty
#define SUPN 128
#define EPSV 1e-6f
#define FULLM 0xffffffffu
#define NBLK2 98

// ---- persistent scratch. .bss zeros == cleared state; k2 tail re-clears each launch ----
__device__ float g_wihT[ND * 3 * ND];   // [k][j] j in [0,192), coalesced for lane=j
__device__ float g_whhT[ND * 3 * ND];
__device__ float g_cq[2][NB][ND];
__device__ int   g_nsup;
__device__ int   g_supk[SUPN];     // packed (b<<17)|e
__device__ int   g_sups[SUPN];     // hash slot holding (ep, hist)
__device__ int   g_hkey[HSZ];
__device__ float g_hep[HSZ];
__device__ float g_hhist[HSZ][ND];
__device__ int   g_h2key[HSZ2];
__device__ float g_h2ep[HSZ2];
__device__ int   g_done;

__device__ __forceinline__ float sigm(float x) { return 1.0f / (1.0f + expf(-x)); }

// ================= K0: weight transposes + cq matmul (small grid) =================
__global__ void k0(const float* __restrict__ rel_emb, const float* __restrict__ W_step,
                   const float* __restrict__ b_step, const float* __restrict__ w_ih,
                   const float* __restrict__ w_hh, const int* __restrict__ query)
{
    int idx = blockIdx.x * 256 + threadIdx.x;          // 0 .. 12287
    if (idx < ND * 3 * ND) {
        int k = idx / (3 * ND), j = idx % (3 * ND);
        g_wihT[idx] = w_ih[j * ND + k];
        g_whhT[idx] = w_hh[j * ND + k];
    }
    // block 0: cq[step][b][d] = tanh(rel_emb[query[b]] . W_step[step][:,d] + b_step[step][d])
    if (blockIdx.x == 0) {
        for (int o = threadIdx.x; o < 2 * NB * ND; o += 256) {
            int step = o >> 8, rem = o & 255, b = rem >> 6, d = rem & 63;
            int q = query[b];
            float acc = b_step[step * ND + d];
            const float* re = rel_emb + q * ND;
            const float* W  = W_step + step * ND * ND + d;
            #pragma unroll 8
            for (int i = 0; i < ND; i++) acc += re[i] * W[i * ND];
            g_cq[step][b][d] = tanhf(acc);
        }
    }
}

// ======== warp-cooperative hop-1 GRU (h = 0), coalesced transposed weights ========
__device__ __forceinline__ void warp_hop1(int t, int b, int lane,
    const int* __restrict__ kb, const float* __restrict__ rel_emb,
    const float* __restrict__ b_ih, const float* __restrict__ b_hh,
    const float* __restrict__ w_cls, const float* __restrict__ b_cls)
{
    int e = kb[3 * t + 1], rid = kb[3 * t + 2];
    int d0 = lane, d1 = lane + 32;
    float rf0 = rel_emb[rid * ND + d0];
    float rf1 = rel_emb[rid * ND + d1];
    float a0 = b_ih[d0], a1 = b_ih[ND + d0], a2 = b_ih[2 * ND + d0];
    float a3 = b_ih[d1], a4 = b_ih[ND + d1], a5 = b_ih[2 * ND + d1];
    #pragma unroll
    for (int k = 0; k < ND; k++) {
        float f = __shfl_sync(FULLM, (k < 32) ? rf0 : rf1, k & 31);
        const float* wt = g_wihT + k * (3 * ND);
        a0 += f * wt[d0];      a1 += f * wt[ND + d0]; a2 += f * wt[2 * ND + d0];
        a3 += f * wt[d1];      a4 += f * wt[ND + d1]; a5 += f * wt[2 * ND + d1];
    }
    float r0 = sigm(a0 + b_hh[d0]);
    float z0 = sigm(a1 + b_hh[ND + d0]);
    float n0 = tanhf(a2 + r0 * b_hh[2 * ND + d0]);
    float tr0 = (1.f - z0) * n0;                        // h = 0
    float r1 = sigm(a3 + b_hh[d1]);
    float z1 = sigm(a4 + b_hh[ND + d1]);
    float n1 = tanhf(a5 + r1 * b_hh[2 * ND + d1]);
    float tr1 = (1.f - z1) * n1;

    float red = tr0 * g_cq[0][b][d0] * w_cls[d0]
              + tr1 * g_cq[0][b][d1] * w_cls[d1];
    #pragma unroll
    for (int off = 16; off; off >>= 1) red += __shfl_xor_sync(FULLM, red, off);
    float p = sigm(red + b_cls[0]);                     // obj_p = 1 * p

    int slot = 0;
    if (lane == 0) {
        int key1 = b * NE + e + 1;                      // +1: 0 means empty
        unsigned h = ((unsigned)key1 * 2654435761u) & (HSZ - 1);
        for (;;) {
            int prev = atomicCAS(&g_hkey[h], 0, key1);
            if (prev == 0) {
                int j = atomicAdd(&g_nsup, 1);
                if (j < SUPN) { g_supk[j] = (b << 17) | e; g_sups[j] = (int)h; }
                slot = (int)h; break;
            }
            if (prev == key1) { slot = (int)h; break; }
            h = (h + 1) & (HSZ - 1);
        }
        atomicAdd(&g_hep[slot], p);
    }
    slot = __shfl_sync(FULLM, slot, 0);
    atomicAdd(&g_hhist[slot][d0], tr0 * p);
    atomicAdd(&g_hhist[slot][d1], tr1 * p);
}

// ========== K1: kb scan with direct start[] gather + inline hop-1 GRU ==========
__global__ void k1(const int* __restrict__ kb, const float* __restrict__ start,
                   const float* __restrict__ rel_emb,
                   const float* __restrict__ b_ih, const float* __restrict__ b_hh,
                   const float* __restrict__ w_cls, const float* __restrict__ b_cls)
{
    int c = blockIdx.x * 256 + threadIdx.x;             // chunk of 4 triples
    int lane = threadIdx.x & 31;
    bool valid = c < NT / 4;
    int ss0 = -1, ss1 = -1, ss2 = -1, ss3 = -1;
    if (valid) {
        const int4* kb4 = (const int4*)kb;
        int4 v0 = kb4[3 * c], v1 = kb4[3 * c + 1], v2 = kb4[3 * c + 2];
        ss0 = v0.x; ss1 = v0.w; ss2 = v1.z; ss3 = v2.y;
    }
    int ssa[4] = { ss0, ss1, ss2, ss3 };
    #pragma unroll
    for (int j = 0; j < 4; j++) {
        int s = ssa[j];
        int t_mine = 4 * c + j;
        #pragma unroll
        for (int b = 0; b < NB; b++) {
            bool hit = valid && (start[b * NE + (valid ? s : 0)] != 0.0f);  // one-hot: exact 1.0
            unsigned m = __ballot_sync(FULLM, hit);
            while (m) {
                int src = __ffs(m) - 1; m &= m - 1;
                int t = __shfl_sync(FULLM, t_mine, src);
                warp_hop1(t, b, lane, kb, rel_emb, b_ih, b_hh, w_cls, b_cls);
            }
        }
    }
}

// ======== warp-cooperative hop-2 full GRU, coalesced transposed weights ========
__device__ __forceinline__ void warp_hop2(int t, int b, int slot, int lane,
    const int* __restrict__ kb, const float* __restrict__ rel_emb,
    const float* __restrict__ b_ih, const float* __restrict__ b_hh,
    const float* __restrict__ w_cls, const float* __restrict__ b_cls)
{
    int e = kb[3 * t + 1], rid = kb[3 * t + 2];
    int d0 = lane, d1 = lane + 32;
    float ep = g_hep[slot];
    float rf0 = rel_emb[rid * ND + d0];
    float rf1 = rel_emb[rid * ND + d1];
    float h0 = g_hhist[slot][d0] / (ep + EPSV);
    float h1 = g_hhist[slot][d1] / (ep + EPSV);

    float x0 = b_ih[d0], x1 = b_ih[ND + d0], x2 = b_ih[2 * ND + d0];
    float x3 = b_ih[d1], x4 = b_ih[ND + d1], x5 = b_ih[2 * ND + d1];
    float y0 = b_hh[d0], y1 = b_hh[ND + d0], y2 = b_hh[2 * ND + d0];
    float y3 = b_hh[d1], y4 = b_hh[ND + d1], y5 = b_hh[2 * ND + d1];
    #pragma unroll
    for (int k = 0; k < ND; k++) {
        float f  = __shfl_sync(FULLM, (k < 32) ? rf0 : rf1, k & 31);
        float hh = __shfl_sync(FULLM, (k < 32) ? h0  : h1,  k & 31);
        const float* wti = g_wihT + k * (3 * ND);
        const float* wth = g_whhT + k * (3 * ND);
        x0 += f * wti[d0];      x1 += f * wti[ND + d0]; x2 += f * wti[2 * ND + d0];
        x3 += f * wti[d1];      x4 += f * wti[ND + d1]; x5 += f * wti[2 * ND + d1];
        y0 += hh * wth[d0];     y1 += hh * wth[ND + d0]; y2 += hh * wth[2 * ND + d0];
        y3 += hh * wth[d1];     y4 += hh * wth[ND + d1]; y5 += hh * wth[2 * ND + d1];
    }
    float r0 = sigm(x0 + y0), z0 = sigm(x1 + y1);
    float n0 = tanhf(x2 + r0 * y2);
    float tr0 = (1.f - z0) * n0 + z0 * h0;
    float r1 = sigm(x3 + y3), z1 = sigm(x4 + y4);
    float n1 = tanhf(x5 + r1 * y5);
    float tr1 = (1.f - z1) * n1 + z1 * h1;

    float red = tr0 * g_cq[1][b][d0] * w_cls[d0]
              + tr1 * g_cq[1][b][d1] * w_cls[d1];
    #pragma unroll
    for (int off = 16; off; off >>= 1) red += __shfl_xor_sync(FULLM, red, off);

    if (lane == 0) {
        float p = sigm(red + b_cls[0]);
        float contrib = fminf(ep, 1.f) * p;             // last_e0 * trans_prob
        int key1 = b * NE + e + 1;
        unsigned h = ((unsigned)key1 * 2654435761u) & (HSZ2 - 1);
        for (;;) {
            int prev = atomicCAS(&g_h2key[h], 0, key1);
            if (prev == 0 || prev == key1) break;
            h = (h + 1) & (HSZ2 - 1);
        }
        atomicAdd(&g_h2ep[h], contrib);
    }
}

// ==== K2: out zero + kb scan vs support + inline hop-2 GRU + last-block tail ====
__global__ void k2(const int* __restrict__ kb, const float* __restrict__ rel_emb,
                   const float* __restrict__ b_ih, const float* __restrict__ b_hh,
                   const float* __restrict__ w_cls, const float* __restrict__ b_cls,
                   float* __restrict__ out)
{
    __shared__ int sh_k[SUPN], sh_s[SUPN], sh_ns;
    __shared__ int sh_last;
    if (threadIdx.x == 0) sh_ns = min(g_nsup, SUPN);
    __syncthreads();
    int ns = sh_ns;
    for (int j = threadIdx.x; j < ns; j += 256) { sh_k[j] = g_supk[j]; sh_s[j] = g_sups[j]; }
    __syncthreads();

    int tid = blockIdx.x * 256 + threadIdx.x;
    int lane = threadIdx.x & 31;

    // zero output (poisoned by harness); must complete before tail scatter
    float4* out4 = (float4*)out;
    for (int i = tid; i < (NB * NE) / 4; i += NBLK2 * 256)
        out4[i] = make_float4(0.f, 0.f, 0.f, 0.f);

    // scan kb vs support list + inline hop-2 GRU
    int c = tid;
    bool valid = c < NT / 4;
    int ss0 = -1, ss1 = -1, ss2 = -1, ss3 = -1;
    if (valid) {
        const int4* kb4 = (const int4*)kb;
        int4 v0 = kb4[3 * c], v1 = kb4[3 * c + 1], v2 = kb4[3 * c + 2];
        ss0 = v0.x; ss1 = v0.w; ss2 = v1.z; ss3 = v2.y;
    }
    int ssa[4] = { ss0, ss1, ss2, ss3 };
    #pragma unroll
    for (int j = 0; j < 4; j++) {
        int s = ssa[j];
        int t_mine = 4 * c + j;
        for (int k = 0; k < ns; k++) {
            int key = sh_k[k];
            unsigned m = __ballot_sync(FULLM, valid && s == (key & 0x1FFFF));
            while (m) {
                int src = __ffs(m) - 1; m &= m - 1;
                int t = __shfl_sync(FULLM, t_mine, src);
                warp_hop2(t, key >> 17, sh_s[k], lane, kb, rel_emb,
                          b_ih, b_hh, w_cls, b_cls);
            }
        }
    }

    // last-block tail: scatter + clear scratch
    __threadfence();
    __syncthreads();
    if (threadIdx.x == 0) sh_last = (atomicAdd(&g_done, 1) == NBLK2 - 1);
    __syncthreads();
    if (!sh_last) return;
    __threadfence();

    for (int i = threadIdx.x; i < HSZ2; i += 256) {
        int k1v = g_h2key[i];
        if (k1v) {
            out[k1v - 1] = fminf(g_h2ep[i], 1.f);       // last_e = min(obj_ep, 1)
            g_h2key[i] = 0; g_h2ep[i] = 0.f;
        }
    }
    for (int i = threadIdx.x; i < HSZ; i += 256) { g_hkey[i] = 0; g_hep[i] = 0.f; }
    for (int i = threadIdx.x; i < HSZ * ND; i += 256) ((float*)g_hhist)[i] = 0.f;
    if (threadIdx.x == 0) { g_nsup = 0; g_done = 0; }
}

extern "C" void kernel_launch(void* const* d_in, const int* in_sizes, int n_in,
                              void* d_out, int out_size)
{
    const float* start   = (const float*)d_in[0];
    const float* rel_emb = (const float*)d_in[1];
    const float* W_step  = (const float*)d_in[2];
    const float* b_step  = (const float*)d_in[3];
    const float* w_ih    = (const float*)d_in[4];
    const float* w_hh    = (const float*)d_in[5];
    const float* b_ih    = (const float*)d_in[6];
    const float* b_hh    = (const float*)d_in[7];
    const float* w_cls   = (const float*)d_in[8];
    const float* b_cls   = (const float*)d_in[9];
    const int*   query   = (const int*)d_in[10];
    const int*   kb      = (const int*)d_in[11];
    float* out = (float*)d_out;

    k0<<<48, 256>>>(rel_emb, W_step, b_step, w_ih, w_hh, query);
    k1<<<98, 256>>>(kb, start, rel_emb, b_ih, b_hh, w_cls, b_cls);
    k2<<<NBLK2, 256>>>(kb, rel_emb, b_ih, b_hh, w_cls, b_cls, out);
}